// round 2
// baseline (speedup 1.0000x reference)
#include <cuda_runtime.h>
#include <math.h>

#define M_TOK 64000

// ---------------- scratch ----------------------------------------------------
__device__ float g_A0[M_TOK * 120];
__device__ float g_B [M_TOK * 160];
__device__ float g_Gpart[250 * 121 * 140];
__device__ float g_Gb[121 * 160];
__device__ float g_T1[121 * 160];
__device__ float g_attn[160 * 160];
__device__ float g_P[160 * 160];
__device__ float g_r[160];
__device__ float g_sA0part[250 * 120];
__device__ float g_sA0[120];

// ---------------- branch traits ---------------------------------------------
template <int BR> struct BT;
template <> struct BT<0> { // axi
    static constexpr int D = 140, ND = 120, NDP = 121;
    static constexpr int W0 = 5, W1 = 7, W2 = 4;
    static constexpr int S0 = 48, S1 = 66, S2 = 38;
    static constexpr int PB0 = 1, PB1 = 2, PB2 = 1;
    static constexpr int OUT_OFF = 0;
    static constexpr int IG = 16, JG = 35;
};
template <> struct BT<1> { // cor view (38,38,66)
    static constexpr int D = 112, ND = 48, NDP = 49;
    static constexpr int W0 = 4, W1 = 4, W2 = 7;
    static constexpr int S0 = 38, S1 = 38, S2 = 66;
    static constexpr int PB0 = 1, PB1 = 1, PB2 = 2;
    static constexpr int OUT_OFF = 7704576;
    static constexpr int IG = 7, JG = 28;
};
template <> struct BT<2> { // sag view (38,78,48)
    static constexpr int D = 160, ND = 36, NDP = 37;
    static constexpr int W0 = 4, W1 = 8, W2 = 5;
    static constexpr int S0 = 38, S1 = 78, S2 = 48;
    static constexpr int PB0 = 1, PB1 = 1, PB2 = 1;
    static constexpr int OUT_OFF = 13804032;
    static constexpr int IG = 5, JG = 40;
};

template <int BR> __device__ __forceinline__ int raw_index(int c, int z0, int z1, int z2);
template <> __device__ __forceinline__ int raw_index<0>(int c, int z0, int z1, int z2) {
    return ((c * 48 + z0) * 66 + z1) * 38 + z2;
}
template <> __device__ __forceinline__ int raw_index<1>(int c, int z0, int z1, int z2) {
    return ((c * 38 + z0) * 66 + z2) * 38 + z1;
}
template <> __device__ __forceinline__ int raw_index<2>(int c, int z0, int z1, int z2) {
    return ((c * 48 + z2) * 78 + z1) * 38 + z0;
}

// distinct Gram row u -> atlas base column ((b0*6+b1)*4+b2, dims 5,6,4)
template <int BR> __device__ __forceinline__ int distcol(int u);
template <> __device__ __forceinline__ int distcol<0>(int u) { return u; }
template <> __device__ __forceinline__ int distcol<1>(int u) {
    int u0 = u / 12, u1 = (u % 12) / 4, u2 = u % 4;
    return (u0 * 6 + 2 * u1) * 4 + u2;
}
template <> __device__ __forceinline__ int distcol<2>(int u) {
    int u0 = u / 9, u1 = (u % 9) / 3, u2 = u % 3;
    return (u0 * 6 + 2 * u1) * 4 + u2;
}

// branch column i -> (distinct row u, base column bc)
template <int BR> __device__ __forceinline__ void imaps(int i, int& u, int& bc);
template <> __device__ __forceinline__ void imaps<0>(int i, int& u, int& bc) {
    int b0 = i / 28, r = i % 28, b1 = r / 4, b2 = r % 4;
    int m1 = b1 ? b1 - 1 : 0;
    u = (b0 * 6 + m1) * 4 + b2;  bc = u;
}
template <> __device__ __forceinline__ void imaps<1>(int i, int& u, int& bc) {
    int b0 = i / 28, r = i % 28, b1 = r / 7, b2 = r % 7;
    int v1 = b1 ? b1 - 1 : 0;  int v2 = b2 >> 1;
    u = (b0 * 3 + v1) * 4 + v2;  bc = (b0 * 6 + 2 * v1) * 4 + v2;
}
template <> __device__ __forceinline__ void imaps<2>(int i, int& u, int& bc) {
    int b0 = i / 40, r = i % 40, b1 = r / 5, b2 = r % 5;
    int v1 = (b1 < 4) ? 0 : ((b1 - 2) >> 1);
    int v2 = (b2 < 2) ? 0 : ((b2 < 3) ? 1 : 2);
    u = (b0 * 3 + v1) * 3 + v2;  bc = (b0 * 6 + 2 * v1) * 4 + v2;
}

// ---------------- builds ------------------------------------------------------
__global__ void k_build_A0(const float* __restrict__ atlas) {
    int idx = blockIdx.x * blockDim.x + threadIdx.x;
    int m = idx / 120, col = idx % 120;
    int c = m / 1000, rm_ = m % 1000;
    int i0 = rm_ / 100, i1 = (rm_ / 10) % 10, i2 = rm_ % 10;
    int b0 = col / 24, b1 = (col / 4) % 6, b2 = col % 4;
    int z0 = i0 * 5 + b0 - 2, z1 = i1 * 6 + b1 - 2, z2 = i2 * 4 + b2 - 1;
    float v = 0.f;
    if ((unsigned)z0 < 46u && (unsigned)z1 < 56u && (unsigned)z2 < 38u)
        v = atlas[((c * 46 + z0) * 56 + z1) * 38 + z2];
    g_A0[idx] = v;
}

__global__ void k_sA0_part() {
    int c = threadIdx.x;
    if (c >= 120) return;
    int m0 = blockIdx.x * 256;
    float s = 0.f;
    for (int k = 0; k < 256; k++) s += g_A0[(m0 + k) * 120 + c];
    g_sA0part[blockIdx.x * 120 + c] = s;
}
__global__ void k_sA0_red() {
    int c = threadIdx.x;
    if (c >= 120) return;
    float s = 0.f;
    for (int p = 0; p < 250; p++) s += g_sA0part[p * 120 + c];
    g_sA0[c] = s;
}

template <int BR> __global__ void k_build_B(const float* __restrict__ in) {
    using T = BT<BR>;
    int idx = blockIdx.x * blockDim.x + threadIdx.x;
    int m = idx / T::D, col = idx % T::D;
    int c = m / 1000, rm_ = m % 1000;
    int i0 = rm_ / 100, i1 = (rm_ / 10) % 10, i2 = rm_ % 10;
    int b0 = col / (T::W1 * T::W2), rc = col % (T::W1 * T::W2);
    int b1 = rc / T::W2, b2 = rc % T::W2;
    int z0 = i0 * T::W0 + b0 - T::PB0;
    int z1 = i1 * T::W1 + b1 - T::PB1;
    int z2 = i2 * T::W2 + b2 - T::PB2;
    float v = 0.f;
    if ((unsigned)z0 < (unsigned)T::S0 && (unsigned)z1 < (unsigned)T::S1 &&
        (unsigned)z2 < (unsigned)T::S2)
        v = in[raw_index<BR>(c, z0, z1, z2)];
    g_B[idx] = v;
}

// ---------------- Gram GEMM (split-K 250x256, deterministic) -----------------
template <int BR> __global__ __launch_bounds__(640) void k_gemmG() {
    using T = BT<BR>;
    constexpr int IG = T::IG, JG = T::JG, PADI = IG * 8, NT = IG * JG;
    __shared__ __align__(16) float As[8][PADI];
    __shared__ __align__(16) float Bs[8][T::D];
    int tid = threadIdx.x;
    int jg = tid % JG, ig = tid / JG;
    float acc[8][4];
#pragma unroll
    for (int r = 0; r < 8; r++)
#pragma unroll
        for (int cc = 0; cc < 4; cc++) acc[r][cc] = 0.f;

    int m0 = blockIdx.x * 256;
    for (int kc = 0; kc < 32; kc++) {
        int mb = m0 + kc * 8;
        for (int t = tid; t < 8 * PADI; t += NT) {
            int k = t / PADI, u = t % PADI;
            float v;
            if (u < T::ND)       v = g_A0[(mb + k) * 120 + distcol<BR>(u)];
            else if (u == T::ND) v = 1.0f;
            else                 v = 0.0f;
            As[k][u] = v;
        }
        for (int t = tid; t < 8 * T::D; t += NT) {
            int k = t / T::D, j = t % T::D;
            Bs[k][j] = g_B[(mb + k) * T::D + j];
        }
        __syncthreads();
#pragma unroll
        for (int k = 0; k < 8; k++) {
            float4 a0 = *(const float4*)&As[k][ig * 8];
            float4 a1 = *(const float4*)&As[k][ig * 8 + 4];
            float4 bb = *(const float4*)&Bs[k][jg * 4];
            float a[8] = {a0.x, a0.y, a0.z, a0.w, a1.x, a1.y, a1.z, a1.w};
            float b[4] = {bb.x, bb.y, bb.z, bb.w};
#pragma unroll
            for (int r = 0; r < 8; r++)
#pragma unroll
                for (int cc = 0; cc < 4; cc++) acc[r][cc] += a[r] * b[cc];
        }
        __syncthreads();
    }
    int base = blockIdx.x * (T::NDP * T::D);
#pragma unroll
    for (int r = 0; r < 8; r++) {
        int u = ig * 8 + r;
        if (u < T::NDP)
#pragma unroll
            for (int cc = 0; cc < 4; cc++)
                g_Gpart[base + u * T::D + jg * 4 + cc] = acc[r][cc];
    }
}

template <int BR> __global__ void k_reduceG() {
    using T = BT<BR>;
    int idx = blockIdx.x * blockDim.x + threadIdx.x;
    if (idx >= T::NDP * T::D) return;
    float s = 0.f;
    for (int p = 0; p < 250; p++) s += g_Gpart[p * T::NDP * T::D + idx];
    g_Gb[idx] = s;
}

// ---------------- T1 = Gb * Wk ------------------------------------------------
template <int BR> __global__ void k_T1(const float* __restrict__ Wk) {
    using T = BT<BR>;
    __shared__ float grow[T::D];
    int u = blockIdx.x, j = threadIdx.x;
    grow[j] = g_Gb[u * T::D + j];
    __syncthreads();
    float s = 0.f;
#pragma unroll 4
    for (int jp = 0; jp < T::D; jp++) s += grow[jp] * Wk[jp * T::D + j];
    g_T1[u * T::D + j] = s;
}

// ---------------- S, softmax, r ----------------------------------------------
template <int BR> __global__ void k_S(const float* __restrict__ Wq,
                                      const float* __restrict__ bq,
                                      const float* __restrict__ bk,
                                      const float* __restrict__ bv) {
    using T = BT<BR>;
    constexpr int D = T::D;
    __shared__ float red[256];
    __shared__ int   rm_s[D];
    __shared__ float sc[3];
    int i = blockIdx.x, j = threadIdx.x;
    int uj, bcj; imaps<BR>(j, uj, bcj);
    rm_s[j] = uj;

    red[j] = Wq[j * D + i] * g_sA0[bcj];
    for (int p = D + j; p < 256; p += D) red[p] = 0.f;
    __syncthreads();
    for (int st = 128; st > 0; st >>= 1) {
        if (j < st) red[j] += red[j + st];
        __syncthreads();
    }
    if (j == 0) sc[0] = red[0];
    __syncthreads();

    float s = 0.f;
#pragma unroll 4
    for (int i2 = 0; i2 < D; i2++)
        s += Wq[i2 * D + i] * g_T1[rm_s[i2] * D + j];
    float bkj = bk[j];
    s += sc[0] * bkj + bq[i] * (g_T1[T::ND * D + j] + 64000.0f * bkj);

    red[j] = s;
    for (int p = D + j; p < 256; p += D) red[p] = -3.4e38f;
    __syncthreads();
    for (int st = 128; st > 0; st >>= 1) {
        if (j < st) red[j] = fmaxf(red[j], red[j + st]);
        __syncthreads();
    }
    if (j == 0) sc[1] = red[0];
    __syncthreads();
    float e = expf(s - sc[1]);
    red[j] = e;
    for (int p = D + j; p < 256; p += D) red[p] = 0.f;
    __syncthreads();
    for (int st = 128; st > 0; st >>= 1) {
        if (j < st) red[j] += red[j + st];
        __syncthreads();
    }
    if (j == 0) sc[2] = red[0];
    __syncthreads();
    float inv = 1.0f / sc[2];
    g_attn[i * D + j] = e * inv;

    red[j] = e * bv[j];
    for (int p = D + j; p < 256; p += D) red[p] = 0.f;
    __syncthreads();
    for (int st = 128; st > 0; st >>= 1) {
        if (j < st) red[j] += red[j + st];
        __syncthreads();
    }
    if (j == 0) g_r[i] = red[0] * inv;
}

// ---------------- P[l][i] = sum_j Wv[l][j] attn[i][j] -------------------------
template <int BR> __global__ void k_P(const float* __restrict__ Wv) {
    using T = BT<BR>;
    __shared__ float arow[T::D];
    int i = blockIdx.x, l = threadIdx.x;
    arow[l] = g_attn[i * T::D + l];
    __syncthreads();
    float p = 0.f;
#pragma unroll 4
    for (int jj = 0; jj < T::D; jj++) p += Wv[l * T::D + jj] * arow[jj];
    g_P[l * T::D + i] = p;
}

// ---------------- cross = B*P + r, fold+crop+scatter --------------------------
template <int BR> __global__ __launch_bounds__(640, 1) void k_cross(float* __restrict__ out) {
    using T = BT<BR>;
    constexpr int D = T::D, JG = T::JG, NT = 16 * JG;
    constexpr int BSROW = 132;
    extern __shared__ float dynsm[];
    float* Bs = dynsm;
    float* Ps = Bs + D * BSROW;
    float* rs = Ps + D * D;

    int tid = threadIdx.x;
    int jg = tid % JG, ig = tid / JG;
    int m0 = blockIdx.x * 128;

    for (int t = tid; t < 128 * (D / 4); t += NT) {
        int mm = t / (D / 4), kv = t % (D / 4);
        float4 v = *(const float4*)&g_B[(m0 + mm) * D + kv * 4];
        Bs[(kv * 4 + 0) * BSROW + mm] = v.x;
        Bs[(kv * 4 + 1) * BSROW + mm] = v.y;
        Bs[(kv * 4 + 2) * BSROW + mm] = v.z;
        Bs[(kv * 4 + 3) * BSROW + mm] = v.w;
    }
    for (int t = tid; t < D * (D / 4); t += NT) {
        int row = t / (D / 4), kv = t % (D / 4);
        *(float4*)&Ps[row * D + kv * 4] = *(const float4*)&g_P[row * D + kv * 4];
    }
    for (int t = tid; t < D; t += NT) rs[t] = g_r[t];
    __syncthreads();

    float acc[8][4];
#pragma unroll
    for (int r = 0; r < 8; r++)
#pragma unroll
        for (int cc = 0; cc < 4; cc++) acc[r][cc] = 0.f;

    int mb = ig * 8, jb = jg * 4;
#pragma unroll 4
    for (int k = 0; k < D; k++) {
        float4 a0 = *(const float4*)&Bs[k * BSROW + mb];
        float4 a1 = *(const float4*)&Bs[k * BSROW + mb + 4];
        float4 bb = *(const float4*)&Ps[k * D + jb];
        float a[8] = {a0.x, a0.y, a0.z, a0.w, a1.x, a1.y, a1.z, a1.w};
        float b[4] = {bb.x, bb.y, bb.z, bb.w};
#pragma unroll
        for (int r = 0; r < 8; r++)
#pragma unroll
            for (int cc = 0; cc < 4; cc++) acc[r][cc] += a[r] * b[cc];
    }

#pragma unroll
    for (int r = 0; r < 8; r++) {
        int m = m0 + mb + r;
        int c = m / 1000, rm_ = m % 1000;
        int i0 = rm_ / 100, i1 = (rm_ / 10) % 10, i2 = rm_ % 10;
        int z0b = i0 * T::W0 - T::PB0;
        int z1b = i1 * T::W1 - T::PB1;
        int z2b = i2 * T::W2 - T::PB2;
#pragma unroll
        for (int cc = 0; cc < 4; cc++) {
            int i = jb + cc;
            int b0 = i / (T::W1 * T::W2), rc = i % (T::W1 * T::W2);
            int b1 = rc / T::W2, b2 = rc % T::W2;
            int z0 = z0b + b0, z1 = z1b + b1, z2 = z2b + b2;
            if ((unsigned)z0 < (unsigned)T::S0 && (unsigned)z1 < (unsigned)T::S1 &&
                (unsigned)z2 < (unsigned)T::S2)
                out[T::OUT_OFF + raw_index<BR>(c, z0, z1, z2)] = acc[r][cc] + rs[i];
        }
    }
}

// ---------------- host --------------------------------------------------------
template <int BR>
static void run_branch(const float* in, const float* Wq, const float* bq,
                       const float* Wk, const float* bk,
                       const float* Wv, const float* bv, float* out) {
    using T = BT<BR>;
    k_build_B<BR><<<(M_TOK * T::D) / 256, 256>>>(in);
    k_gemmG<BR><<<250, T::IG * T::JG>>>();
    k_reduceG<BR><<<(T::NDP * T::D + 255) / 256, 256>>>();
    k_T1<BR><<<T::NDP, T::D>>>(Wk);
    k_S<BR><<<T::D, T::D>>>(Wq, bq, bk, bv);
    k_P<BR><<<T::D, T::D>>>(Wv);
    constexpr int SMEM = (T::D * 132 + T::D * T::D + T::D) * 4;
    cudaFuncSetAttribute(k_cross<BR>, cudaFuncAttributeMaxDynamicSharedMemorySize, SMEM);
    k_cross<BR><<<500, 16 * T::JG, SMEM>>>(out);
}

extern "C" void kernel_launch(void* const* d_in, const int* in_sizes, int n_in,
                              void* d_out, int out_size) {
    (void)in_sizes; (void)n_in; (void)out_size;
    const float* axi   = (const float*)d_in[0];
    const float* cor   = (const float*)d_in[1];
    const float* sag   = (const float*)d_in[2];
    const float* atlas = (const float*)d_in[3];
    float* out = (float*)d_out;

    k_build_A0<<<30000, 256>>>(atlas);
    k_sA0_part<<<250, 128>>>();
    k_sA0_red<<<1, 128>>>();

    run_branch<0>(axi, (const float*)d_in[4],  (const float*)d_in[5],
                       (const float*)d_in[6],  (const float*)d_in[7],
                       (const float*)d_in[8],  (const float*)d_in[9],  out);
    run_branch<1>(cor, (const float*)d_in[10], (const float*)d_in[11],
                       (const float*)d_in[12], (const float*)d_in[13],
                       (const float*)d_in[14], (const float*)d_in[15], out);
    run_branch<2>(sag, (const float*)d_in[16], (const float*)d_in[17],
                       (const float*)d_in[18], (const float*)d_in[19],
                       (const float*)d_in[20], (const float*)d_in[21], out);
}